// round 2
// baseline (speedup 1.0000x reference)
#include <cuda_runtime.h>
#include <cstdint>

// Problem dims
#define BSZ   4096
#define LSEQ  64
#define EDIM  32
#define HDIM  32
#define GDIM  256
#define F2DIM 512
#define ADIM  1000
#define NSF   32768   // 8 * BSZ
#define NS    36864   // 9 * BSZ

// ---------------- scratch (device globals: allocation-free) ----------------
__device__ float d_hq[BSZ * HDIM];                       // [4096, 32]
__device__ float d_X0[(size_t)NSF * 65];                 // [32768, 65]
__device__ float d_X1[(size_t)NSF * GDIM];               // [32768, 256]
__device__ float d_X2[(size_t)NSF * GDIM];               // [32768, 256]
__device__ float d_gsum[(size_t)BSZ * GDIM];             // [4096, 256]
__device__ float d_Y1[(size_t)BSZ * GDIM];               // [4096, 256]
__device__ float d_Y2[(size_t)BSZ * F2DIM];              // [4096, 512]

// Packed LSTM weights: [e or k][j*4 + gate(i,f,g,o)], Wih then Whh
__device__ float d_pkq[2 * 32 * 128];
__device__ float d_pks[2 * 32 * 128];
__device__ float d_pkbq[128];
__device__ float d_pkbs[128];

struct SfPtrs { const int* p[8]; };

__device__ __forceinline__ float fsig(float x)  { return 1.f / (1.f + __expf(-x)); }
__device__ __forceinline__ float ftanh_(float x){ return 2.f / (1.f + __expf(-2.f * x)) - 1.f; }

// ---------------------------------------------------------------------------
// Pack LSTM weights into gate-interleaved layout:
//   pk[e*128 + j*4 + g] = W[(g*32 + j)*32 + e]
// ---------------------------------------------------------------------------
__global__ void pack_kernel(
    const float* __restrict__ qWih, const float* __restrict__ qWhh, const float* __restrict__ qb,
    const float* __restrict__ sWih, const float* __restrict__ sWhh, const float* __restrict__ sb)
{
    int idx = blockIdx.x * blockDim.x + threadIdx.x;   // 0 .. 4095
    if (idx < 4096) {
        int e   = idx >> 7;       // 0..31
        int rem = idx & 127;      // j*4+g
        int j   = rem >> 2;
        int g   = rem & 3;
        int src = (g * 32 + j) * 32 + e;
        d_pkq[idx]        = qWih[src];
        d_pkq[4096 + idx] = qWhh[src];
        d_pks[idx]        = sWih[src];
        d_pks[4096 + idx] = sWhh[src];
    }
    if (idx < 128) {
        int j = idx >> 2, g = idx & 3;
        d_pkbq[idx] = qb[g * 32 + j];
        d_pkbs[idx] = sb[g * 32 + j];
    }
}

// ---------------------------------------------------------------------------
// LSTM: warp-per-sample, lane-per-hidden-unit. 4 samples per 128-thread block.
// Blocks [0,1024) = q stream, [1024,9216) = 8 sf streams (block-uniform weights).
// Per-thread state: h, c scalars + 4 gate accumulators. No register arrays.
// ---------------------------------------------------------------------------
__global__ __launch_bounds__(128) void lstm_kernel(
    const int* __restrict__ q, SfPtrs sf, const float* __restrict__ emb)
{
    __shared__ __align__(16) float sWih[32 * 128];
    __shared__ __align__(16) float sWhh[32 * 128];
    __shared__ __align__(16) float sB[128];

    const bool isQ = (blockIdx.x < (BSZ / 4));
    const float* src  = isQ ? d_pkq  : d_pks;
    const float* srcb = isQ ? d_pkbq : d_pkbs;
    for (int i = threadIdx.x; i < 4096; i += 128) {
        sWih[i] = src[i];
        sWhh[i] = src[4096 + i];
    }
    if (threadIdx.x < 128) sB[threadIdx.x] = srcb[threadIdx.x];
    __syncthreads();

    const int w = threadIdx.x >> 5;     // warp in block = sample slot
    const int j = threadIdx.x & 31;     // hidden unit
    const int s = blockIdx.x * 4 + w;   // global sample

    const int* tok;
    int b, ss = 0;
    if (isQ) {
        b = s;
        tok = q + (size_t)b * LSEQ;
    } else {
        ss = s - BSZ;
        int r = ss >> 12;
        b = ss & (BSZ - 1);
        tok = sf.p[r] + (size_t)b * LSEQ;
    }

    // Preload all 64 tokens into 2 regs per lane
    const int tk0 = tok[j];
    const int tk1 = tok[32 + j];

    const float4 bj = *reinterpret_cast<const float4*>(&sB[j * 4]); // bi,bf,bg,bo

    float h = 0.f, c = 0.f;

    for (int t = 0; t < LSEQ; t++) {
        const int sel   = (t < 32) ? tk0 : tk1;
        const int token = __shfl_sync(0xffffffffu, sel, t & 31);
        const float xj  = emb[(size_t)token * EDIM + j];

        float ai = bj.x, af = bj.y, ag = bj.z, ao = bj.w;

#pragma unroll
        for (int e = 0; e < 32; e++) {
            const float xe = __shfl_sync(0xffffffffu, xj, e);
            const float4 wv = *reinterpret_cast<const float4*>(&sWih[e * 128 + j * 4]);
            ai += wv.x * xe; af += wv.y * xe; ag += wv.z * xe; ao += wv.w * xe;
        }
#pragma unroll
        for (int k = 0; k < 32; k++) {
            const float hk = __shfl_sync(0xffffffffu, h, k);
            const float4 uv = *reinterpret_cast<const float4*>(&sWhh[k * 128 + j * 4]);
            ai += uv.x * hk; af += uv.y * hk; ag += uv.z * hk; ao += uv.w * hk;
        }

        c = fsig(af) * c + fsig(ai) * ftanh_(ag);
        h = fsig(ao) * ftanh_(c);
    }

    if (isQ) d_hq[(size_t)b * HDIM + j] = h;
    else     d_X0[(size_t)ss * 65 + j]  = h;
}

// Build the rest of the g1 input: X0[s, 32:64] = hq[b], X0[s, 64] = r
__global__ void build_x0_kernel()
{
    int s = blockIdx.x * blockDim.x + threadIdx.x;
    if (s >= NSF) return;
    int r = s >> 12;
    int b = s & (BSZ - 1);
    float* row = d_X0 + (size_t)s * 65;
    const float* hq = d_hq + (size_t)b * HDIM;
#pragma unroll
    for (int j = 0; j < HDIM; j++) row[HDIM + j] = hq[j];
    row[64] = (float)r;
}

// ---------------------------------------------------------------------------
// Generic fp32 GEMM: C[M,N] = act(A[M,K] @ W[N,K]^T + bias)
// 128x128 block tile, BK=16, 256 threads, 8x8 micro-tile. M % 128 == 0 assumed.
// ---------------------------------------------------------------------------
__global__ __launch_bounds__(256) void gemm_kernel(
    const float* __restrict__ A, const float* __restrict__ W,
    const float* __restrict__ bias, float* __restrict__ C,
    int M, int N, int K, int doRelu)
{
    __shared__ __align__(16) float sA[16][132];
    __shared__ __align__(16) float sW[16][132];

    const int bm = blockIdx.y * 128;
    const int bn = blockIdx.x * 128;
    const int tid = threadIdx.x;
    const int tx = tid & 15;
    const int ty = tid >> 4;

    float acc[8][8];
#pragma unroll
    for (int i = 0; i < 8; i++)
#pragma unroll
        for (int j = 0; j < 8; j++) acc[i][j] = 0.f;

    for (int k0 = 0; k0 < K; k0 += 16) {
#pragma unroll
        for (int i = 0; i < 8; i++) {
            int e  = tid + i * 256;      // 0..2047
            int m  = e >> 4;             // 0..127
            int kk = e & 15;
            int gk = k0 + kk;
            sA[kk][m] = (gk < K) ? A[(size_t)(bm + m) * K + gk] : 0.f;
            int n = bn + m;
            sW[kk][m] = (gk < K && n < N) ? W[(size_t)n * K + gk] : 0.f;
        }
        __syncthreads();
#pragma unroll
        for (int kk = 0; kk < 16; kk++) {
            float a[8], w[8];
            float4 a0 = *reinterpret_cast<const float4*>(&sA[kk][ty * 8]);
            float4 a1 = *reinterpret_cast<const float4*>(&sA[kk][ty * 8 + 4]);
            float4 w0 = *reinterpret_cast<const float4*>(&sW[kk][tx * 8]);
            float4 w1 = *reinterpret_cast<const float4*>(&sW[kk][tx * 8 + 4]);
            a[0]=a0.x; a[1]=a0.y; a[2]=a0.z; a[3]=a0.w;
            a[4]=a1.x; a[5]=a1.y; a[6]=a1.z; a[7]=a1.w;
            w[0]=w0.x; w[1]=w0.y; w[2]=w0.z; w[3]=w0.w;
            w[4]=w1.x; w[5]=w1.y; w[6]=w1.z; w[7]=w1.w;
#pragma unroll
            for (int i = 0; i < 8; i++)
#pragma unroll
                for (int j = 0; j < 8; j++) acc[i][j] += a[i] * w[j];
        }
        __syncthreads();
    }

#pragma unroll
    for (int i = 0; i < 8; i++) {
        int m = bm + ty * 8 + i;
#pragma unroll
        for (int j = 0; j < 8; j++) {
            int n = bn + tx * 8 + j;
            if (n < N) {
                float v = acc[i][j] + bias[n];
                if (doRelu) v = fmaxf(v, 0.f);
                C[(size_t)m * N + n] = v;
            }
        }
    }
}

// gsum[b,n] = sum_{r=0..7} X2[r*BSZ + b, n]
__global__ void reduce8_kernel()
{
    int idx = blockIdx.x * 256 + threadIdx.x;   // over 4096*256
    int b = idx >> 8;
    int n = idx & 255;
    float sum = 0.f;
#pragma unroll
    for (int r = 0; r < 8; r++)
        sum += d_X2[((size_t)(r * BSZ + b)) * GDIM + n];
    d_gsum[idx] = sum;
}

// ---------------------------------------------------------------------------
extern "C" void kernel_launch(void* const* d_in, const int* in_sizes, int n_in,
                              void* d_out, int out_size)
{
    const int*   q    = (const int*)d_in[0];
    SfPtrs sf;
    for (int i = 0; i < 8; i++) sf.p[i] = (const int*)d_in[1 + i];
    const float* emb  = (const float*)d_in[9];
    const float* qWih = (const float*)d_in[10];
    const float* qWhh = (const float*)d_in[11];
    const float* qb   = (const float*)d_in[12];
    const float* sWih = (const float*)d_in[13];
    const float* sWhh = (const float*)d_in[14];
    const float* sb   = (const float*)d_in[15];
    const float* g1W  = (const float*)d_in[16];
    const float* g1b  = (const float*)d_in[17];
    const float* g2W  = (const float*)d_in[18];
    const float* g2b  = (const float*)d_in[19];
    const float* g3W  = (const float*)d_in[20];
    const float* g3b  = (const float*)d_in[21];
    const float* g4W  = (const float*)d_in[22];
    const float* g4b  = (const float*)d_in[23];
    const float* f1W  = (const float*)d_in[24];
    const float* f1b  = (const float*)d_in[25];
    const float* f2W  = (const float*)d_in[26];
    const float* f2b  = (const float*)d_in[27];
    const float* f3W  = (const float*)d_in[28];
    const float* f3b  = (const float*)d_in[29];
    float* out = (float*)d_out;

    // Resolve scratch symbol addresses (host-side query; capture-safe).
    void *pX0, *pX1, *pX2, *pGsum, *pY1, *pY2;
    cudaGetSymbolAddress(&pX0,   d_X0);
    cudaGetSymbolAddress(&pX1,   d_X1);
    cudaGetSymbolAddress(&pX2,   d_X2);
    cudaGetSymbolAddress(&pGsum, d_gsum);
    cudaGetSymbolAddress(&pY1,   d_Y1);
    cudaGetSymbolAddress(&pY2,   d_Y2);
    const float* X0 = (const float*)pX0;
    float* X1 = (float*)pX1;
    float* X2 = (float*)pX2;
    float* Gs = (float*)pGsum;
    float* Y1 = (float*)pY1;
    float* Y2 = (float*)pY2;

    // 0) pack LSTM weights into gate-interleaved layout
    pack_kernel<<<16, 256>>>(qWih, qWhh, qb, sWih, sWhh, sb);

    // 1) fused LSTM (q + 8 sf streams), warp-per-sample
    lstm_kernel<<<NS / 4, 128>>>(q, sf, emb);

    // 2) assemble g1 input [32768, 65]
    build_x0_kernel<<<(NSF + 255) / 256, 256>>>();

    // 3) g-MLP: 4 layers with ReLU
    gemm_kernel<<<dim3(GDIM / 128, NSF / 128), 256>>>(X0, g1W, g1b, X1, NSF, GDIM, 65, 1);
    gemm_kernel<<<dim3(GDIM / 128, NSF / 128), 256>>>(X1, g2W, g2b, X2, NSF, GDIM, GDIM, 1);
    gemm_kernel<<<dim3(GDIM / 128, NSF / 128), 256>>>(X2, g3W, g3b, X1, NSF, GDIM, GDIM, 1);
    gemm_kernel<<<dim3(GDIM / 128, NSF / 128), 256>>>(X1, g4W, g4b, X2, NSF, GDIM, GDIM, 1);

    // 4) segment-sum over 8 relations
    reduce8_kernel<<<(BSZ * GDIM) / 256, 256>>>();

    // 5) f-head
    gemm_kernel<<<dim3(GDIM / 128,  BSZ / 128), 256>>>(Gs, f1W, f1b, Y1, BSZ, GDIM,  GDIM,  1);
    gemm_kernel<<<dim3(F2DIM / 128, BSZ / 128), 256>>>(Y1, f2W, f2b, Y2, BSZ, F2DIM, GDIM,  1);
    gemm_kernel<<<dim3((ADIM + 127) / 128, BSZ / 128), 256>>>(Y2, f3W, f3b, out, BSZ, ADIM, F2DIM, 0);
}

// round 3
// speedup vs baseline: 1.7091x; 1.7091x over previous
#include <cuda_runtime.h>
#include <cstdint>

// Problem dims
#define BSZ   4096
#define LSEQ  64
#define EDIM  32
#define HDIM  32
#define GDIM  256
#define F2DIM 512
#define ADIM  1000
#define NSF   32768   // 8 * BSZ
#define NS    36864   // 9 * BSZ

// ---------------- scratch (device globals: allocation-free) ----------------
__device__ float d_hq[BSZ * HDIM];                       // [4096, 32]
__device__ float d_X0[(size_t)NSF * 65];                 // [32768, 65]
__device__ float d_X1[(size_t)NSF * GDIM];               // [32768, 256]
__device__ float d_X2[(size_t)NSF * GDIM];               // [32768, 256]
__device__ float d_gsum[(size_t)BSZ * GDIM];             // [4096, 256]
__device__ float d_Y1[(size_t)BSZ * GDIM];               // [4096, 256]
__device__ float d_Y2[(size_t)BSZ * F2DIM];              // [4096, 512]

// Packed LSTM weights: [e or k][j*4 + gate(i,f,g,o)], Wih then Whh
__device__ float d_pkq[2 * 32 * 128];
__device__ float d_pks[2 * 32 * 128];
__device__ float d_pkbq[128];
__device__ float d_pkbs[128];

struct SfPtrs { const int* p[8]; };

__device__ __forceinline__ float ftanh_(float x) {
    float r;
    asm("tanh.approx.f32 %0, %1;" : "=f"(r) : "f"(x));
    return r;
}
__device__ __forceinline__ float fsig(float x) {
    // sigmoid(x) = 0.5*tanh(0.5x) + 0.5
    return fmaf(ftanh_(0.5f * x), 0.5f, 0.5f);
}

// ---------------------------------------------------------------------------
// Pack LSTM weights into gate-interleaved layout:
//   pk[e*128 + j*4 + g] = W[(g*32 + j)*32 + e]
// ---------------------------------------------------------------------------
__global__ void pack_kernel(
    const float* __restrict__ qWih, const float* __restrict__ qWhh, const float* __restrict__ qb,
    const float* __restrict__ sWih, const float* __restrict__ sWhh, const float* __restrict__ sb)
{
    int idx = blockIdx.x * blockDim.x + threadIdx.x;   // 0 .. 4095
    if (idx < 4096) {
        int e   = idx >> 7;       // 0..31
        int rem = idx & 127;      // j*4+g
        int j   = rem >> 2;
        int g   = rem & 3;
        int src = (g * 32 + j) * 32 + e;
        d_pkq[idx]        = qWih[src];
        d_pkq[4096 + idx] = qWhh[src];
        d_pks[idx]        = sWih[src];
        d_pks[4096 + idx] = sWhh[src];
    }
    if (idx < 128) {
        int j = idx >> 2, g = idx & 3;
        d_pkbq[idx] = qb[g * 32 + j];
        d_pkbs[idx] = sb[g * 32 + j];
    }
}

// ---------------------------------------------------------------------------
// LSTM: thread-per-sample. 128 samples per block (288 blocks total).
// Weights are block-uniform -> every weight fetch is a BROADCAST LDS128
// (1 crossbar cycle, amortized over 32 samples). x[] and h[] live in
// registers (statically indexed). Runtime-j state (h, c) bounces through
// thread-private smem columns -> conflict-free, no __syncthreads in the
// time loop.
// Dynamic smem layout (floats):
//   [0,4096)      sWih packed
//   [4096,8192)   sWhh packed
//   [8192,8320)   bias packed
//   [8320,12416)  hb  [32][128]
//   [12416,16512) cs  [32][128]
// ---------------------------------------------------------------------------
#define LSTM_SMEM_FLOATS 16512

__global__ __launch_bounds__(128) void lstm_kernel(
    const int* __restrict__ q, SfPtrs sf, const float* __restrict__ emb)
{
    extern __shared__ float sm[];
    float* sWih = sm;
    float* sWhh = sm + 4096;
    float* sB   = sm + 8192;
    float* hb   = sm + 8320;
    float* cs   = sm + 12416;

    const int tid = threadIdx.x;
    const bool isQ = (blockIdx.x < (BSZ / 128));
    const float* src  = isQ ? d_pkq  : d_pks;
    const float* srcb = isQ ? d_pkbq : d_pkbs;

    for (int i = tid; i < 4096; i += 128) {
        sWih[i] = src[i];
        sWhh[i] = src[4096 + i];
    }
    sB[tid] = srcb[tid];

#pragma unroll
    for (int j = 0; j < 32; j++) {
        hb[j * 128 + tid] = 0.f;
        cs[j * 128 + tid] = 0.f;
    }
    __syncthreads();

    const int s = blockIdx.x * 128 + tid;
    const int* tok;
    int b, ss = 0;
    if (isQ) {
        b = s;
        tok = q + (size_t)b * LSEQ;
    } else {
        ss = s - BSZ;
        int r = ss >> 12;
        b = ss & (BSZ - 1);
        tok = sf.p[r] + (size_t)b * LSEQ;
    }

    for (int t = 0; t < LSEQ; t++) {
        // per-sample embedding row -> registers
        const int token = tok[t];
        const float4* er = reinterpret_cast<const float4*>(emb + (size_t)token * EDIM);
        float x[EDIM];
#pragma unroll
        for (int v = 0; v < 8; v++) {
            float4 e = er[v];
            x[4*v] = e.x; x[4*v+1] = e.y; x[4*v+2] = e.z; x[4*v+3] = e.w;
        }
        // previous hidden state -> registers (thread-private column)
        float h[HDIM];
#pragma unroll
        for (int k = 0; k < 32; k++) h[k] = hb[k * 128 + tid];

        for (int j = 0; j < 32; j++) {      // runtime loop: small I$ footprint
            const float4 b4 = *reinterpret_cast<const float4*>(&sB[j * 4]);
            float ai = b4.x, af = b4.y, ag = b4.z, ao = b4.w;
#pragma unroll
            for (int k = 0; k < 32; k++) {
                const float4 wv = *reinterpret_cast<const float4*>(&sWih[k * 128 + j * 4]);
                ai += wv.x * x[k]; af += wv.y * x[k]; ag += wv.z * x[k]; ao += wv.w * x[k];
                const float4 uv = *reinterpret_cast<const float4*>(&sWhh[k * 128 + j * 4]);
                ai += uv.x * h[k]; af += uv.y * h[k]; ag += uv.z * h[k]; ao += uv.w * h[k];
            }
            float cc = cs[j * 128 + tid];
            cc = fsig(af) * cc + fsig(ai) * ftanh_(ag);
            cs[j * 128 + tid] = cc;
            hb[j * 128 + tid] = fsig(ao) * ftanh_(cc);
        }
    }

    if (isQ) {
        float* dst = d_hq + (size_t)b * HDIM;
#pragma unroll
        for (int j = 0; j < 32; j++) dst[j] = hb[j * 128 + tid];
    } else {
        float* row = d_X0 + (size_t)ss * 65;
#pragma unroll
        for (int j = 0; j < 32; j++) row[j] = hb[j * 128 + tid];
    }
}

// Build the rest of the g1 input: X0[s, 32:64] = hq[b], X0[s, 64] = r
__global__ void build_x0_kernel()
{
    int s = blockIdx.x * blockDim.x + threadIdx.x;
    if (s >= NSF) return;
    int r = s >> 12;
    int b = s & (BSZ - 1);
    float* row = d_X0 + (size_t)s * 65;
    const float* hq = d_hq + (size_t)b * HDIM;
#pragma unroll
    for (int j = 0; j < HDIM; j++) row[HDIM + j] = hq[j];
    row[64] = (float)r;
}

// ---------------------------------------------------------------------------
// fp32 GEMM: C[M,N] = act(A[M,K] @ W[N,K]^T + bias)
// 128x64 block tile, BK=16, 256 threads, 8x4 micro-tile (~70 regs -> 3 CTA/SM).
// M % 128 == 0 assumed; N, K arbitrary.
// ---------------------------------------------------------------------------
__global__ __launch_bounds__(256) void gemm_kernel(
    const float* __restrict__ A, const float* __restrict__ W,
    const float* __restrict__ bias, float* __restrict__ C,
    int M, int N, int K, int doRelu)
{
    __shared__ __align__(16) float sA[16][132];
    __shared__ __align__(16) float sW[16][68];

    const int bm = blockIdx.y * 128;
    const int bn = blockIdx.x * 64;
    const int tid = threadIdx.x;
    const int tx = tid & 15;      // n: 16 x 4
    const int ty = tid >> 4;      // m: 16 x 8

    float acc[8][4];
#pragma unroll
    for (int i = 0; i < 8; i++)
#pragma unroll
        for (int j = 0; j < 4; j++) acc[i][j] = 0.f;

    for (int k0 = 0; k0 < K; k0 += 16) {
#pragma unroll
        for (int i = 0; i < 8; i++) {        // 2048 A elements
            int e  = tid + i * 256;
            int m  = e >> 4;
            int kk = e & 15;
            int gk = k0 + kk;
            sA[kk][m] = (gk < K) ? A[(size_t)(bm + m) * K + gk] : 0.f;
        }
#pragma unroll
        for (int i = 0; i < 4; i++) {        // 1024 W elements
            int e  = tid + i * 256;
            int n  = e >> 4;
            int kk = e & 15;
            int gk = k0 + kk;
            sW[kk][n] = (gk < K && (bn + n) < N) ? W[(size_t)(bn + n) * K + gk] : 0.f;
        }
        __syncthreads();
#pragma unroll
        for (int kk = 0; kk < 16; kk++) {
            float a[8], w[4];
            float4 a0 = *reinterpret_cast<const float4*>(&sA[kk][ty * 8]);
            float4 a1 = *reinterpret_cast<const float4*>(&sA[kk][ty * 8 + 4]);
            float4 w0 = *reinterpret_cast<const float4*>(&sW[kk][tx * 4]);
            a[0]=a0.x; a[1]=a0.y; a[2]=a0.z; a[3]=a0.w;
            a[4]=a1.x; a[5]=a1.y; a[6]=a1.z; a[7]=a1.w;
            w[0]=w0.x; w[1]=w0.y; w[2]=w0.z; w[3]=w0.w;
#pragma unroll
            for (int i = 0; i < 8; i++)
#pragma unroll
                for (int j = 0; j < 4; j++) acc[i][j] += a[i] * w[j];
        }
        __syncthreads();
    }

#pragma unroll
    for (int i = 0; i < 8; i++) {
        int m = bm + ty * 8 + i;
#pragma unroll
        for (int j = 0; j < 4; j++) {
            int n = bn + tx * 4 + j;
            if (n < N) {
                float v = acc[i][j] + bias[n];
                if (doRelu) v = fmaxf(v, 0.f);
                C[(size_t)m * N + n] = v;
            }
        }
    }
}

// gsum[b,n] = sum_{r=0..7} X2[r*BSZ + b, n]
__global__ void reduce8_kernel()
{
    int idx = blockIdx.x * 256 + threadIdx.x;   // over 4096*256
    int b = idx >> 8;
    int n = idx & 255;
    float sum = 0.f;
#pragma unroll
    for (int r = 0; r < 8; r++)
        sum += d_X2[((size_t)(r * BSZ + b)) * GDIM + n];
    d_gsum[idx] = sum;
}

// ---------------------------------------------------------------------------
extern "C" void kernel_launch(void* const* d_in, const int* in_sizes, int n_in,
                              void* d_out, int out_size)
{
    const int*   q    = (const int*)d_in[0];
    SfPtrs sf;
    for (int i = 0; i < 8; i++) sf.p[i] = (const int*)d_in[1 + i];
    const float* emb  = (const float*)d_in[9];
    const float* qWih = (const float*)d_in[10];
    const float* qWhh = (const float*)d_in[11];
    const float* qb   = (const float*)d_in[12];
    const float* sWih = (const float*)d_in[13];
    const float* sWhh = (const float*)d_in[14];
    const float* sb   = (const float*)d_in[15];
    const float* g1W  = (const float*)d_in[16];
    const float* g1b  = (const float*)d_in[17];
    const float* g2W  = (const float*)d_in[18];
    const float* g2b  = (const float*)d_in[19];
    const float* g3W  = (const float*)d_in[20];
    const float* g3b  = (const float*)d_in[21];
    const float* g4W  = (const float*)d_in[22];
    const float* g4b  = (const float*)d_in[23];
    const float* f1W  = (const float*)d_in[24];
    const float* f1b  = (const float*)d_in[25];
    const float* f2W  = (const float*)d_in[26];
    const float* f2b  = (const float*)d_in[27];
    const float* f3W  = (const float*)d_in[28];
    const float* f3b  = (const float*)d_in[29];
    float* out = (float*)d_out;

    // Resolve scratch symbol addresses (host-side query; capture-safe).
    void *pX0, *pX1, *pX2, *pGsum, *pY1, *pY2;
    cudaGetSymbolAddress(&pX0,   d_X0);
    cudaGetSymbolAddress(&pX1,   d_X1);
    cudaGetSymbolAddress(&pX2,   d_X2);
    cudaGetSymbolAddress(&pGsum, d_gsum);
    cudaGetSymbolAddress(&pY1,   d_Y1);
    cudaGetSymbolAddress(&pY2,   d_Y2);
    const float* X0 = (const float*)pX0;
    float* X1 = (float*)pX1;
    float* X2 = (float*)pX2;
    float* Gs = (float*)pGsum;
    float* Y1 = (float*)pY1;
    float* Y2 = (float*)pY2;

    // Allow >48KB dynamic smem for the LSTM kernel (idempotent).
    static bool attr_set = false;
    if (!attr_set) {
        cudaFuncSetAttribute(lstm_kernel, cudaFuncAttributeMaxDynamicSharedMemorySize,
                             LSTM_SMEM_FLOATS * (int)sizeof(float));
        attr_set = true;
    }

    // 0) pack LSTM weights into gate-interleaved layout
    pack_kernel<<<16, 256>>>(qWih, qWhh, qb, sWih, sWhh, sb);

    // 1) fused LSTM (q + 8 sf streams), thread-per-sample
    lstm_kernel<<<NS / 128, 128, LSTM_SMEM_FLOATS * sizeof(float)>>>(q, sf, emb);

    // 2) assemble g1 input [32768, 65]
    build_x0_kernel<<<(NSF + 255) / 256, 256>>>();

    // 3) g-MLP: 4 layers with ReLU
    gemm_kernel<<<dim3(GDIM / 64, NSF / 128), 256>>>(X0, g1W, g1b, X1, NSF, GDIM, 65, 1);
    gemm_kernel<<<dim3(GDIM / 64, NSF / 128), 256>>>(X1, g2W, g2b, X2, NSF, GDIM, GDIM, 1);
    gemm_kernel<<<dim3(GDIM / 64, NSF / 128), 256>>>(X2, g3W, g3b, X1, NSF, GDIM, GDIM, 1);
    gemm_kernel<<<dim3(GDIM / 64, NSF / 128), 256>>>(X1, g4W, g4b, X2, NSF, GDIM, GDIM, 1);

    // 4) segment-sum over 8 relations
    reduce8_kernel<<<(BSZ * GDIM) / 256, 256>>>();

    // 5) f-head
    gemm_kernel<<<dim3(GDIM / 64,  BSZ / 128), 256>>>(Gs, f1W, f1b, Y1, BSZ, GDIM,  GDIM,  1);
    gemm_kernel<<<dim3(F2DIM / 64, BSZ / 128), 256>>>(Y1, f2W, f2b, Y2, BSZ, F2DIM, GDIM,  1);
    gemm_kernel<<<dim3((ADIM + 63) / 64, BSZ / 128), 256>>>(Y2, f3W, f3b, out, BSZ, ADIM, F2DIM, 0);
}